// round 16
// baseline (speedup 1.0000x reference)
#include <cuda_runtime.h>
#include <cuda_fp16.h>
#include <stdint.h>
#include <math.h>

#define D    4096
#define RK   1024
#define NTOT (1u << 24)     // 4^12 probability entries
#define PITB 80             // smem row pitch in BYTES (40 fp16) — conflict-free
#define TPIT 132            // epilogue transpose pitch (floats)

// ---------------------------------------------------------------------------
// Scratch (__device__ globals per allocation rules).
// ---------------------------------------------------------------------------
__device__ float gA_re[NTOT];
__device__ float gA_im[NTOT];
__device__ float gB_re[NTOT];
__device__ float gB_im[NTOT];
__device__ __half gFr[(size_t)D * RK];   // fp16(Ur)
__device__ __half gFi[(size_t)D * RK];   // fp16(Ui)
__device__ float g_inv_trace;

// ---------------------------------------------------------------------------
static __device__ __forceinline__ void mma16(float c[4], const uint32_t a[4],
                                             const uint32_t b[2]) {
    asm volatile(
        "mma.sync.aligned.m16n8k16.row.col.f32.f16.f16.f32 "
        "{%0,%1,%2,%3}, {%4,%5,%6,%7}, {%8,%9}, {%0,%1,%2,%3};\n"
        : "+f"(c[0]), "+f"(c[1]), "+f"(c[2]), "+f"(c[3])
        : "r"(a[0]), "r"(a[1]), "r"(a[2]), "r"(a[3]), "r"(b[0]), "r"(b[1]));
}
static __device__ __forceinline__ uint32_t lds32(const char* base, int off) {
    return *(const uint32_t*)(base + off);
}

// ---------------------------------------------------------------------------
// Pack: fp16(Ur), fp16(Ui).
// ---------------------------------------------------------------------------
__global__ void __launch_bounds__(256) pack_split(const float* __restrict__ Ur,
                                                  const float* __restrict__ Ui)
{
    unsigned e = blockIdx.x * 256u + threadIdx.x;   // 0 .. 4M-1
    gFr[e] = __float2half_rn(Ur[e]);
    gFi[e] = __float2half_rn(Ui[e]);
}

// ---------------------------------------------------------------------------
// rho = U U^H via fp16 single-pass mma.sync (m16n8k16). (R15, proven.)
// ---------------------------------------------------------------------------
__global__ void __launch_bounds__(256, 1) gemm_mma()
{
    extern __shared__ char sm[];    // 2 stages * 4 planes * 128*PITB bytes

    const int tid  = threadIdx.x;
    const int lane = tid & 31;
    const int wid  = tid >> 5;
    const int gid  = lane >> 2;     // 0..7
    const int tig  = lane & 3;      // 0..3
    const int wm   = wid >> 2;      // 0..1
    const int wn   = wid & 3;       // 0..3

    // triangular tile index
    int l = blockIdx.x;
    int bi = (int)((sqrtf(8.0f * (float)l + 1.0f) - 1.0f) * 0.5f);
    while ((bi + 1) * (bi + 2) / 2 <= l) bi++;
    while (bi * (bi + 1) / 2 > l) bi--;
    int bj = l - bi * (bi + 1) / 2;
    const int row0 = bi * 128, col0 = bj * 128;

    const int PLNB = 128 * PITB;    // 10240 B per plane
    const int BUFB = 4 * PLNB;      // 40960 B per stage

    // plane order: 0 Ar, 1 Ai, 2 Br, 3 Bi
    auto load_chunk = [&](int buf, int k0) {
        char* base = sm + buf * BUFB;
#pragma unroll
        for (int u = 0; u < 8; u++) {
            int i = tid + u * 256;          // 0..2047 16B slots
            int plane = i >> 9;             // 0..3
            int rem = i & 511;
            int r = rem >> 2;               // 0..127
            int q = rem & 3;                // 16B slot within 64B row-chunk
            const __half* arr = (plane & 1) ? gFi : gFr;
            int baser = (plane < 2) ? row0 : col0;
            const __half* src = arr + (size_t)(baser + r) * RK + k0 + q * 8;
            uint32_t dst = (uint32_t)__cvta_generic_to_shared(
                base + plane * PLNB + r * PITB + q * 16);
            asm volatile("cp.async.cg.shared.global [%0], [%1], 16;"
                         :: "r"(dst), "l"(src));
        }
    };

    float accre[4][4][4], accim[4][4][4];
#pragma unroll
    for (int a = 0; a < 4; a++)
#pragma unroll
        for (int b = 0; b < 4; b++)
#pragma unroll
            for (int q = 0; q < 4; q++) { accre[a][b][q] = 0.f; accim[a][b][q] = 0.f; }

    load_chunk(0, 0);
    asm volatile("cp.async.commit_group;");

#pragma unroll 1
    for (int c = 0; c < 32; c++) {
        if (c + 1 < 32) load_chunk((c + 1) & 1, (c + 1) * 32);
        asm volatile("cp.async.commit_group;");
        asm volatile("cp.async.wait_group 1;");
        __syncthreads();

        const char* bb = sm + (c & 1) * BUFB;

#pragma unroll
        for (int kk = 0; kk < 2; kk++) {      // two k16 halves of the 32-chunk
            const int kbyte = kk * 32 + tig * 4;   // within-row byte offset

            uint32_t Br[4][2], Bi[4][2];
#pragma unroll
            for (int nf = 0; nf < 4; nf++) {
                int n = (wn * 32 + nf * 8 + gid) * PITB;
                Br[nf][0] = lds32(bb + 2 * PLNB, n + kbyte);
                Br[nf][1] = lds32(bb + 2 * PLNB, n + kbyte + 16);
                Bi[nf][0] = lds32(bb + 3 * PLNB, n + kbyte);
                Bi[nf][1] = lds32(bb + 3 * PLNB, n + kbyte + 16);
            }

            uint32_t Ar[4][4], Ai[4][4];
#pragma unroll
            for (int mf = 0; mf < 4; mf++) {
                int r = (wm * 64 + mf * 16 + gid) * PITB;
                Ar[mf][0] = lds32(bb,        r + kbyte);
                Ar[mf][1] = lds32(bb,        r + 8 * PITB + kbyte);
                Ar[mf][2] = lds32(bb,        r + kbyte + 16);
                Ar[mf][3] = lds32(bb,        r + 8 * PITB + kbyte + 16);
                Ai[mf][0] = lds32(bb + PLNB, r + kbyte);
                Ai[mf][1] = lds32(bb + PLNB, r + 8 * PITB + kbyte);
                Ai[mf][2] = lds32(bb + PLNB, r + kbyte + 16);
                Ai[mf][3] = lds32(bb + PLNB, r + 8 * PITB + kbyte + 16);
            }
            // re += Ar*Br
#pragma unroll
            for (int mf = 0; mf < 4; mf++)
#pragma unroll
                for (int nf = 0; nf < 4; nf++) mma16(accre[mf][nf], Ar[mf], Br[nf]);
            // im += (-Ar)*Bi  (exact sign flip)
#pragma unroll
            for (int mf = 0; mf < 4; mf++)
#pragma unroll
                for (int q = 0; q < 4; q++) Ar[mf][q] ^= 0x80008000u;
#pragma unroll
            for (int mf = 0; mf < 4; mf++)
#pragma unroll
                for (int nf = 0; nf < 4; nf++) mma16(accim[mf][nf], Ar[mf], Bi[nf]);
            // re += Ai*Bi
#pragma unroll
            for (int mf = 0; mf < 4; mf++)
#pragma unroll
                for (int nf = 0; nf < 4; nf++) mma16(accre[mf][nf], Ai[mf], Bi[nf]);
            // im += Ai*Br
#pragma unroll
            for (int mf = 0; mf < 4; mf++)
#pragma unroll
                for (int nf = 0; nf < 4; nf++) mma16(accim[mf][nf], Ai[mf], Br[nf]);
        }
        __syncthreads();
    }

    // drain cp.async before reusing smem for the transpose
    asm volatile("cp.async.wait_group 0;");
    __syncthreads();

    // ---- main tile writes (row-major, float2 per store) ----
#pragma unroll
    for (int mf = 0; mf < 4; mf++)
#pragma unroll
        for (int nf = 0; nf < 4; nf++) {
            unsigned r  = row0 + wm * 64 + mf * 16 + gid;
            unsigned cc = col0 + wn * 32 + nf * 8 + 2 * tig;
            const float* cr = accre[mf][nf];
            const float* ci = accim[mf][nf];
            *(float2*)&gA_re[(size_t)r * D + cc]       = make_float2(cr[0], cr[1]);
            *(float2*)&gA_re[(size_t)(r + 8) * D + cc] = make_float2(cr[2], cr[3]);
            *(float2*)&gA_im[(size_t)r * D + cc]       = make_float2(ci[0], ci[1]);
            *(float2*)&gA_im[(size_t)(r + 8) * D + cc] = make_float2(ci[2], ci[3]);
        }

    // ---- mirror writes via smem transpose (coalesced 512B rows) ----
    if (bi != bj) {
        float* smf = (float*)sm;    // 128 x TPIT floats = 67584 B (< 81920)
#pragma unroll 1
        for (int pl = 0; pl < 2; pl++) {
            float sgn = pl ? -1.f : 1.f;
#pragma unroll
            for (int mf = 0; mf < 4; mf++)
#pragma unroll
                for (int nf = 0; nf < 4; nf++) {
                    int rL  = wm * 64 + mf * 16 + gid;
                    int ccL = wn * 32 + nf * 8 + 2 * tig;
                    const float* v = pl ? accim[mf][nf] : accre[mf][nf];
                    smf[(ccL)     * TPIT + rL]     = sgn * v[0];
                    smf[(ccL + 1) * TPIT + rL]     = sgn * v[1];
                    smf[(ccL)     * TPIT + rL + 8] = sgn * v[2];
                    smf[(ccL + 1) * TPIT + rL + 8] = sgn * v[3];
                }
            __syncthreads();
            float* gout = pl ? gA_im : gA_re;
#pragma unroll
            for (int r8 = 0; r8 < 16; r8++) {
                int mr = wid * 16 + r8;
                float4 v = *(float4*)&smf[mr * TPIT + lane * 4];
                *(float4*)&gout[(size_t)(col0 + mr) * D + row0 + lane * 4] = v;
            }
            __syncthreads();
        }
    }
}

// ---------------------------------------------------------------------------
// trace: sum of re diagonal of rho -> 1/trace
// ---------------------------------------------------------------------------
__global__ void trace_kernel()
{
    __shared__ float red[256];
    float s = 0.f;
    for (int i = threadIdx.x; i < D; i += 256)
        s += gA_re[(size_t)i * D + i];
    red[threadIdx.x] = s;
    __syncthreads();
    for (int w = 128; w; w >>= 1) {
        if (threadIdx.x < w) red[threadIdx.x] += red[threadIdx.x + w];
        __syncthreads();
    }
    if (threadIdx.x == 0) g_inv_trace = 1.0f / red[0];
}

// ---------------------------------------------------------------------------
// Fused 2-qubit partial-trace sweep (factored, two 4-term complex stages).
// g0: gid offset — enables per-k-group chained launches so that sweeps 3..6
// of each group read their input from L2 (64MB working set << 126MB L2).
// dir=0: A->B, dir=1: B->A. wim=0 skips imag store (last sweep).
// ---------------------------------------------------------------------------
__global__ void __launch_bounds__(256) qmt_sweep(int dir,
                                                 const float* __restrict__ Mr,
                                                 const float* __restrict__ Mi,
                                                 int lc, int wim, unsigned g0)
{
    const float* __restrict__ in_re = dir ? gB_re : gA_re;
    const float* __restrict__ in_im = dir ? gB_im : gA_im;
    float* __restrict__ o_re = dir ? gA_re : gB_re;
    float* __restrict__ o_im = dir ? gA_im : gB_im;

    __shared__ float sr[16], si[16];   // M[s,i,j] at s*4+i*2+j
    int tid = threadIdx.x;
    if (tid < 16) { sr[tid] = Mr[tid]; si[tid] = Mi[tid]; }
    __syncthreads();

    unsigned gid = g0 + blockIdx.x * 256u + (unsigned)tid;   // 0 .. 2^20-1
    unsigned cp = 1u << lc;
    unsigned t = gid & (cp - 1u);
    unsigned a = (gid >> lc) & (cp - 1u);
    unsigned k = gid >> (2 * lc);
    unsigned base_in = k << (2 * lc + 4);

    float xr[16], xi[16];
#pragma unroll
    for (int J = 0; J < 4; J++)
#pragma unroll
        for (int I = 0; I < 4; I++) {
            unsigned off = base_in
                         + ((((unsigned)J << lc) + a) << (lc + 2))
                         + ((unsigned)I << lc) + t;
            xr[J * 4 + I] = in_re[off];
            xi[J * 4 + I] = in_im[off];
        }

    // stage 1: contract (j1,i1): y[s1][(j2,i2)]
    float yr[16], yi[16];
#pragma unroll
    for (int s1 = 0; s1 < 4; s1++)
#pragma unroll
        for (int j2 = 0; j2 < 2; j2++)
#pragma unroll
            for (int i2 = 0; i2 < 2; i2++) {
                float ar = 0.f, ai = 0.f;
#pragma unroll
                for (int j1 = 0; j1 < 2; j1++)
#pragma unroll
                    for (int i1 = 0; i1 < 2; i1++) {
                        float mr = sr[s1 * 4 + i1 * 2 + j1];
                        float mi = si[s1 * 4 + i1 * 2 + j1];
                        float vr = xr[(j1 * 2 + j2) * 4 + i1 * 2 + i2];
                        float vi = xi[(j1 * 2 + j2) * 4 + i1 * 2 + i2];
                        ar = fmaf(mr, vr, ar); ar = fmaf(-mi, vi, ar);
                        ai = fmaf(mr, vi, ai); ai = fmaf(mi, vr, ai);
                    }
                yr[s1 * 4 + j2 * 2 + i2] = ar;
                yi[s1 * 4 + j2 * 2 + i2] = ai;
            }

    // stage 2: contract (j2,i2)
#pragma unroll
    for (int s1 = 0; s1 < 4; s1++)
#pragma unroll
        for (int s2 = 0; s2 < 4; s2++) {
            float aR = 0.f, aI = 0.f;
#pragma unroll
            for (int j2 = 0; j2 < 2; j2++)
#pragma unroll
                for (int i2 = 0; i2 < 2; i2++) {
                    float mr = sr[s2 * 4 + i2 * 2 + j2];
                    float mi = si[s2 * 4 + i2 * 2 + j2];
                    float vr = yr[s1 * 4 + j2 * 2 + i2];
                    float vi = yi[s1 * 4 + j2 * 2 + i2];
                    aR = fmaf(mr, vr, aR); aR = fmaf(-mi, vi, aR);
                    aI = fmaf(mr, vi, aI); aI = fmaf(mi, vr, aI);
                }
            unsigned off = (((k << 4) + (unsigned)(s1 * 4 + s2)) << (2 * lc))
                         + (a << lc) + t;
            o_re[off] = aR;
            if (wim) o_im[off] = aI;
        }
}

// ---------------------------------------------------------------------------
// Gather: out[i] = P_all[idx[i]] / trace (real plane only; int32 indices).
// ---------------------------------------------------------------------------
__global__ void gather_kernel(const int* __restrict__ idx,
                              float* __restrict__ out, int n)
{
    int i = blockIdx.x * 256 + threadIdx.x;
    if (i < n) out[i] = gA_re[(unsigned)idx[i] & (NTOT - 1u)] * g_inv_trace;
}

// ---------------------------------------------------------------------------
extern "C" void kernel_launch(void* const* d_in, const int* in_sizes, int n_in,
                              void* d_out, int out_size)
{
    const float* params = (const float*)d_in[0];      // (2, 4096, 1024)
    const float* Mr = (const float*)d_in[1];          // (4,2,2)
    const float* Mi = (const float*)d_in[2];          // (4,2,2)
    const int* idx = (const int*)d_in[3];             // (1e6,) int32
    float* out = (float*)d_out;

    const float* Ur = params;
    const float* Ui = params + (size_t)D * RK;

    pack_split<<<16384, 256>>>(Ur, Ui);

    const int smem_bytes = 2 * 4 * 128 * PITB;        // 81920
    cudaFuncSetAttribute(gemm_mma,
                         cudaFuncAttributeMaxDynamicSharedMemorySize, smem_bytes);
    gemm_mma<<<528, 256, smem_bytes>>>();

    trace_kernel<<<1, 256>>>();

    // Sweep 1 over the full array (k=1, no grouping possible): A -> B.
    qmt_sweep<<<4096, 256>>>(0, Mr, Mi, 10, 1, 0u);

    // Sweeps 2..6 chained per k-group (8 groups): each group's ping-pong
    // working set is 64MB — L2-resident across the chain.
    const unsigned GRP = 8;
    const unsigned per = (1u << 20) / GRP;            // 2^17 gids per group
    for (unsigned g = 0; g < GRP; g++) {
        int dir = 1;                                  // sweep 2 reads B
        for (int n = 2; n <= 6; n++) {
            qmt_sweep<<<per / 256, 256>>>(dir, Mr, Mi, 12 - 2 * n,
                                          n < 6 ? 1 : 0, g * per);
            dir ^= 1;
        }
    }
    // 6 sweeps total: final result (real plane) in gA_re.

    int nq = in_sizes[3];
    gather_kernel<<<(nq + 255) / 256, 256>>>(idx, out, nq);
}

// round 17
// speedup vs baseline: 1.3175x; 1.3175x over previous
#include <cuda_runtime.h>
#include <cuda_fp16.h>
#include <stdint.h>
#include <math.h>

#define D    4096
#define RK   1024
#define NTOT (1u << 24)     // 4^12 probability entries
#define PITB 80             // smem row pitch in BYTES (40 fp16) — conflict-free
#define TPIT 132            // epilogue transpose pitch (floats)

// ---------------------------------------------------------------------------
// Scratch (__device__ globals per allocation rules).
// ---------------------------------------------------------------------------
__device__ float gA_re[NTOT];
__device__ float gA_im[NTOT];
__device__ float gB_re[NTOT];
__device__ float gB_im[NTOT];
__device__ __half gFr[(size_t)D * RK];   // fp16(Ur)
__device__ __half gFi[(size_t)D * RK];   // fp16(Ui)
__device__ float g_inv_trace;

// ---------------------------------------------------------------------------
static __device__ __forceinline__ void mma16(float c[4], const uint32_t a[4],
                                             const uint32_t b[2]) {
    asm volatile(
        "mma.sync.aligned.m16n8k16.row.col.f32.f16.f16.f32 "
        "{%0,%1,%2,%3}, {%4,%5,%6,%7}, {%8,%9}, {%0,%1,%2,%3};\n"
        : "+f"(c[0]), "+f"(c[1]), "+f"(c[2]), "+f"(c[3])
        : "r"(a[0]), "r"(a[1]), "r"(a[2]), "r"(a[3]), "r"(b[0]), "r"(b[1]));
}
static __device__ __forceinline__ uint32_t lds32(const char* base, int off) {
    return *(const uint32_t*)(base + off);
}

// ---------------------------------------------------------------------------
// Pack: fp16(Ur), fp16(Ui).
// ---------------------------------------------------------------------------
__global__ void __launch_bounds__(256) pack_split(const float* __restrict__ Ur,
                                                  const float* __restrict__ Ui)
{
    unsigned e = blockIdx.x * 256u + threadIdx.x;   // 0 .. 4M-1
    gFr[e] = __float2half_rn(Ur[e]);
    gFi[e] = __float2half_rn(Ui[e]);
}

// ---------------------------------------------------------------------------
// rho = U U^H via fp16 single-pass mma.sync (m16n8k16). (R15, proven.)
// ---------------------------------------------------------------------------
__global__ void __launch_bounds__(256, 1) gemm_mma()
{
    extern __shared__ char sm[];    // 2 stages * 4 planes * 128*PITB bytes

    const int tid  = threadIdx.x;
    const int lane = tid & 31;
    const int wid  = tid >> 5;
    const int gid  = lane >> 2;     // 0..7
    const int tig  = lane & 3;      // 0..3
    const int wm   = wid >> 2;      // 0..1
    const int wn   = wid & 3;       // 0..3

    // triangular tile index
    int l = blockIdx.x;
    int bi = (int)((sqrtf(8.0f * (float)l + 1.0f) - 1.0f) * 0.5f);
    while ((bi + 1) * (bi + 2) / 2 <= l) bi++;
    while (bi * (bi + 1) / 2 > l) bi--;
    int bj = l - bi * (bi + 1) / 2;
    const int row0 = bi * 128, col0 = bj * 128;

    const int PLNB = 128 * PITB;    // 10240 B per plane
    const int BUFB = 4 * PLNB;      // 40960 B per stage

    // plane order: 0 Ar, 1 Ai, 2 Br, 3 Bi
    auto load_chunk = [&](int buf, int k0) {
        char* base = sm + buf * BUFB;
#pragma unroll
        for (int u = 0; u < 8; u++) {
            int i = tid + u * 256;          // 0..2047 16B slots
            int plane = i >> 9;             // 0..3
            int rem = i & 511;
            int r = rem >> 2;               // 0..127
            int q = rem & 3;                // 16B slot within 64B row-chunk
            const __half* arr = (plane & 1) ? gFi : gFr;
            int baser = (plane < 2) ? row0 : col0;
            const __half* src = arr + (size_t)(baser + r) * RK + k0 + q * 8;
            uint32_t dst = (uint32_t)__cvta_generic_to_shared(
                base + plane * PLNB + r * PITB + q * 16);
            asm volatile("cp.async.cg.shared.global [%0], [%1], 16;"
                         :: "r"(dst), "l"(src));
        }
    };

    float accre[4][4][4], accim[4][4][4];
#pragma unroll
    for (int a = 0; a < 4; a++)
#pragma unroll
        for (int b = 0; b < 4; b++)
#pragma unroll
            for (int q = 0; q < 4; q++) { accre[a][b][q] = 0.f; accim[a][b][q] = 0.f; }

    load_chunk(0, 0);
    asm volatile("cp.async.commit_group;");

#pragma unroll 1
    for (int c = 0; c < 32; c++) {
        if (c + 1 < 32) load_chunk((c + 1) & 1, (c + 1) * 32);
        asm volatile("cp.async.commit_group;");
        asm volatile("cp.async.wait_group 1;");
        __syncthreads();

        const char* bb = sm + (c & 1) * BUFB;

#pragma unroll
        for (int kk = 0; kk < 2; kk++) {      // two k16 halves of the 32-chunk
            const int kbyte = kk * 32 + tig * 4;   // within-row byte offset

            uint32_t Br[4][2], Bi[4][2];
#pragma unroll
            for (int nf = 0; nf < 4; nf++) {
                int n = (wn * 32 + nf * 8 + gid) * PITB;
                Br[nf][0] = lds32(bb + 2 * PLNB, n + kbyte);
                Br[nf][1] = lds32(bb + 2 * PLNB, n + kbyte + 16);
                Bi[nf][0] = lds32(bb + 3 * PLNB, n + kbyte);
                Bi[nf][1] = lds32(bb + 3 * PLNB, n + kbyte + 16);
            }

            uint32_t Ar[4][4], Ai[4][4];
#pragma unroll
            for (int mf = 0; mf < 4; mf++) {
                int r = (wm * 64 + mf * 16 + gid) * PITB;
                Ar[mf][0] = lds32(bb,        r + kbyte);
                Ar[mf][1] = lds32(bb,        r + 8 * PITB + kbyte);
                Ar[mf][2] = lds32(bb,        r + kbyte + 16);
                Ar[mf][3] = lds32(bb,        r + 8 * PITB + kbyte + 16);
                Ai[mf][0] = lds32(bb + PLNB, r + kbyte);
                Ai[mf][1] = lds32(bb + PLNB, r + 8 * PITB + kbyte);
                Ai[mf][2] = lds32(bb + PLNB, r + kbyte + 16);
                Ai[mf][3] = lds32(bb + PLNB, r + 8 * PITB + kbyte + 16);
            }
            // re += Ar*Br
#pragma unroll
            for (int mf = 0; mf < 4; mf++)
#pragma unroll
                for (int nf = 0; nf < 4; nf++) mma16(accre[mf][nf], Ar[mf], Br[nf]);
            // im += (-Ar)*Bi  (exact sign flip)
#pragma unroll
            for (int mf = 0; mf < 4; mf++)
#pragma unroll
                for (int q = 0; q < 4; q++) Ar[mf][q] ^= 0x80008000u;
#pragma unroll
            for (int mf = 0; mf < 4; mf++)
#pragma unroll
                for (int nf = 0; nf < 4; nf++) mma16(accim[mf][nf], Ar[mf], Bi[nf]);
            // re += Ai*Bi
#pragma unroll
            for (int mf = 0; mf < 4; mf++)
#pragma unroll
                for (int nf = 0; nf < 4; nf++) mma16(accre[mf][nf], Ai[mf], Bi[nf]);
            // im += Ai*Br
#pragma unroll
            for (int mf = 0; mf < 4; mf++)
#pragma unroll
                for (int nf = 0; nf < 4; nf++) mma16(accim[mf][nf], Ai[mf], Br[nf]);
        }
        __syncthreads();
    }

    // drain cp.async before reusing smem for the transpose
    asm volatile("cp.async.wait_group 0;");
    __syncthreads();

    // ---- main tile writes (row-major, float2 per store) ----
#pragma unroll
    for (int mf = 0; mf < 4; mf++)
#pragma unroll
        for (int nf = 0; nf < 4; nf++) {
            unsigned r  = row0 + wm * 64 + mf * 16 + gid;
            unsigned cc = col0 + wn * 32 + nf * 8 + 2 * tig;
            const float* cr = accre[mf][nf];
            const float* ci = accim[mf][nf];
            *(float2*)&gA_re[(size_t)r * D + cc]       = make_float2(cr[0], cr[1]);
            *(float2*)&gA_re[(size_t)(r + 8) * D + cc] = make_float2(cr[2], cr[3]);
            *(float2*)&gA_im[(size_t)r * D + cc]       = make_float2(ci[0], ci[1]);
            *(float2*)&gA_im[(size_t)(r + 8) * D + cc] = make_float2(ci[2], ci[3]);
        }

    // ---- mirror writes via smem transpose (coalesced 512B rows) ----
    if (bi != bj) {
        float* smf = (float*)sm;    // 128 x TPIT floats = 67584 B (< 81920)
#pragma unroll 1
        for (int pl = 0; pl < 2; pl++) {
            float sgn = pl ? -1.f : 1.f;
#pragma unroll
            for (int mf = 0; mf < 4; mf++)
#pragma unroll
                for (int nf = 0; nf < 4; nf++) {
                    int rL  = wm * 64 + mf * 16 + gid;
                    int ccL = wn * 32 + nf * 8 + 2 * tig;
                    const float* v = pl ? accim[mf][nf] : accre[mf][nf];
                    smf[(ccL)     * TPIT + rL]     = sgn * v[0];
                    smf[(ccL + 1) * TPIT + rL]     = sgn * v[1];
                    smf[(ccL)     * TPIT + rL + 8] = sgn * v[2];
                    smf[(ccL + 1) * TPIT + rL + 8] = sgn * v[3];
                }
            __syncthreads();
            float* gout = pl ? gA_im : gA_re;
#pragma unroll
            for (int r8 = 0; r8 < 16; r8++) {
                int mr = wid * 16 + r8;
                float4 v = *(float4*)&smf[mr * TPIT + lane * 4];
                *(float4*)&gout[(size_t)(col0 + mr) * D + row0 + lane * 4] = v;
            }
            __syncthreads();
        }
    }
}

// ---------------------------------------------------------------------------
// trace: sum of re diagonal of rho -> 1/trace
// ---------------------------------------------------------------------------
__global__ void trace_kernel()
{
    __shared__ float red[256];
    float s = 0.f;
    for (int i = threadIdx.x; i < D; i += 256)
        s += gA_re[(size_t)i * D + i];
    red[threadIdx.x] = s;
    __syncthreads();
    for (int w = 128; w; w >>= 1) {
        if (threadIdx.x < w) red[threadIdx.x] += red[threadIdx.x + w];
        __syncthreads();
    }
    if (threadIdx.x == 0) g_inv_trace = 1.0f / red[0];
}

// ---------------------------------------------------------------------------
// Fused 2-qubit partial-trace sweep (factored, two 4-term complex stages).
// dir=0: A->B, dir=1: B->A.  (R15, proven; all 5 sweeps write both planes.)
// ---------------------------------------------------------------------------
__global__ void __launch_bounds__(256) qmt_sweep(int dir,
                                                 const float* __restrict__ Mr,
                                                 const float* __restrict__ Mi,
                                                 int lc)
{
    const float* __restrict__ in_re = dir ? gB_re : gA_re;
    const float* __restrict__ in_im = dir ? gB_im : gA_im;
    float* __restrict__ o_re = dir ? gA_re : gB_re;
    float* __restrict__ o_im = dir ? gA_im : gB_im;

    __shared__ float sr[16], si[16];   // M[s,i,j] at s*4+i*2+j
    int tid = threadIdx.x;
    if (tid < 16) { sr[tid] = Mr[tid]; si[tid] = Mi[tid]; }
    __syncthreads();

    unsigned gid = blockIdx.x * 256u + (unsigned)tid;   // 0 .. 2^20-1
    unsigned cp = 1u << lc;
    unsigned t = gid & (cp - 1u);
    unsigned a = (gid >> lc) & (cp - 1u);
    unsigned k = gid >> (2 * lc);
    unsigned base_in = k << (2 * lc + 4);

    float xr[16], xi[16];
#pragma unroll
    for (int J = 0; J < 4; J++)
#pragma unroll
        for (int I = 0; I < 4; I++) {
            unsigned off = base_in
                         + ((((unsigned)J << lc) + a) << (lc + 2))
                         + ((unsigned)I << lc) + t;
            xr[J * 4 + I] = in_re[off];
            xi[J * 4 + I] = in_im[off];
        }

    // stage 1: contract (j1,i1): y[s1][(j2,i2)]
    float yr[16], yi[16];
#pragma unroll
    for (int s1 = 0; s1 < 4; s1++)
#pragma unroll
        for (int j2 = 0; j2 < 2; j2++)
#pragma unroll
            for (int i2 = 0; i2 < 2; i2++) {
                float ar = 0.f, ai = 0.f;
#pragma unroll
                for (int j1 = 0; j1 < 2; j1++)
#pragma unroll
                    for (int i1 = 0; i1 < 2; i1++) {
                        float mr = sr[s1 * 4 + i1 * 2 + j1];
                        float mi = si[s1 * 4 + i1 * 2 + j1];
                        float vr = xr[(j1 * 2 + j2) * 4 + i1 * 2 + i2];
                        float vi = xi[(j1 * 2 + j2) * 4 + i1 * 2 + i2];
                        ar = fmaf(mr, vr, ar); ar = fmaf(-mi, vi, ar);
                        ai = fmaf(mr, vi, ai); ai = fmaf(mi, vr, ai);
                    }
                yr[s1 * 4 + j2 * 2 + i2] = ar;
                yi[s1 * 4 + j2 * 2 + i2] = ai;
            }

    // stage 2: contract (j2,i2)
#pragma unroll
    for (int s1 = 0; s1 < 4; s1++)
#pragma unroll
        for (int s2 = 0; s2 < 4; s2++) {
            float aR = 0.f, aI = 0.f;
#pragma unroll
            for (int j2 = 0; j2 < 2; j2++)
#pragma unroll
                for (int i2 = 0; i2 < 2; i2++) {
                    float mr = sr[s2 * 4 + i2 * 2 + j2];
                    float mi = si[s2 * 4 + i2 * 2 + j2];
                    float vr = yr[s1 * 4 + j2 * 2 + i2];
                    float vi = yi[s1 * 4 + j2 * 2 + i2];
                    aR = fmaf(mr, vr, aR); aR = fmaf(-mi, vi, aR);
                    aI = fmaf(mr, vi, aI); aI = fmaf(mi, vr, aI);
                }
            unsigned off = (((k << 4) + (unsigned)(s1 * 4 + s2)) << (2 * lc))
                         + (a << lc) + t;
            o_re[off] = aR;
            o_im[off] = aI;
        }
}

// ---------------------------------------------------------------------------
// FUSED sweep-6 + gather. After 5 sweeps the array (in gB_*) holds blocks of
// 16 contiguous complex values per k (lc=0 layout: element q = 4*J + I).
// P_all[k*16+S] = sum_q ( MmR[S][q]*xr[q] - MmI[S][q]*xi[q] ), so each query
// idx -> (k = idx>>4, S = idx&15) needs one 64B re block + one 64B im block.
// Mm = Kron(M,M): Mm[(s1,s2)][(2j1+j2)*4+(2i1+i2)] = M[s1,i1,j1]*M[s2,i2,j2]
// (weight construction verified in the R2 full-16x16 sweep kernel).
// ---------------------------------------------------------------------------
__global__ void __launch_bounds__(256) fused_gather(const int* __restrict__ idx,
                                                    const float* __restrict__ Mr,
                                                    const float* __restrict__ Mi,
                                                    float* __restrict__ out, int n)
{
    __shared__ float sMr[256];
    __shared__ float sMi[256];
    int tid = threadIdx.x;
    {
        int S = tid >> 4, rem = tid & 15;
        int J = rem >> 2, I = rem & 3;
        int s1 = S >> 2, s2 = S & 3;
        int j1 = J >> 1, j2 = J & 1;
        int i1 = I >> 1, i2 = I & 1;
        float ar = Mr[s1 * 4 + i1 * 2 + j1], ai = Mi[s1 * 4 + i1 * 2 + j1];
        float br = Mr[s2 * 4 + i2 * 2 + j2], bi = Mi[s2 * 4 + i2 * 2 + j2];
        sMr[tid] = ar * br - ai * bi;
        sMi[tid] = ar * bi + ai * br;
    }
    __syncthreads();

    int i = blockIdx.x * 256 + tid;
    if (i >= n) return;

    unsigned pidx = (unsigned)idx[i] & (NTOT - 1u);
    unsigned k = pidx >> 4;
    unsigned S = pidx & 15u;
    const float* xr = gB_re + (size_t)k * 16;
    const float* xi = gB_im + (size_t)k * 16;

    float4 r0 = *(const float4*)&xr[0],  r1 = *(const float4*)&xr[4];
    float4 r2 = *(const float4*)&xr[8],  r3 = *(const float4*)&xr[12];
    float4 m0 = *(const float4*)&xi[0],  m1 = *(const float4*)&xi[4];
    float4 m2 = *(const float4*)&xi[8],  m3 = *(const float4*)&xi[12];

    const float* wr = sMr + S * 16;
    const float* wi = sMi + S * 16;
    float acc = 0.f;
    acc = fmaf(wr[0],  r0.x, acc); acc = fmaf(-wi[0],  m0.x, acc);
    acc = fmaf(wr[1],  r0.y, acc); acc = fmaf(-wi[1],  m0.y, acc);
    acc = fmaf(wr[2],  r0.z, acc); acc = fmaf(-wi[2],  m0.z, acc);
    acc = fmaf(wr[3],  r0.w, acc); acc = fmaf(-wi[3],  m0.w, acc);
    acc = fmaf(wr[4],  r1.x, acc); acc = fmaf(-wi[4],  m1.x, acc);
    acc = fmaf(wr[5],  r1.y, acc); acc = fmaf(-wi[5],  m1.y, acc);
    acc = fmaf(wr[6],  r1.z, acc); acc = fmaf(-wi[6],  m1.z, acc);
    acc = fmaf(wr[7],  r1.w, acc); acc = fmaf(-wi[7],  m1.w, acc);
    acc = fmaf(wr[8],  r2.x, acc); acc = fmaf(-wi[8],  m2.x, acc);
    acc = fmaf(wr[9],  r2.y, acc); acc = fmaf(-wi[9],  m2.y, acc);
    acc = fmaf(wr[10], r2.z, acc); acc = fmaf(-wi[10], m2.z, acc);
    acc = fmaf(wr[11], r2.w, acc); acc = fmaf(-wi[11], m2.w, acc);
    acc = fmaf(wr[12], r3.x, acc); acc = fmaf(-wi[12], m3.x, acc);
    acc = fmaf(wr[13], r3.y, acc); acc = fmaf(-wi[13], m3.y, acc);
    acc = fmaf(wr[14], r3.z, acc); acc = fmaf(-wi[14], m3.z, acc);
    acc = fmaf(wr[15], r3.w, acc); acc = fmaf(-wi[15], m3.w, acc);

    out[i] = acc * g_inv_trace;
}

// ---------------------------------------------------------------------------
extern "C" void kernel_launch(void* const* d_in, const int* in_sizes, int n_in,
                              void* d_out, int out_size)
{
    const float* params = (const float*)d_in[0];      // (2, 4096, 1024)
    const float* Mr = (const float*)d_in[1];          // (4,2,2)
    const float* Mi = (const float*)d_in[2];          // (4,2,2)
    const int* idx = (const int*)d_in[3];             // (1e6,) int32
    float* out = (float*)d_out;

    const float* Ur = params;
    const float* Ui = params + (size_t)D * RK;

    pack_split<<<16384, 256>>>(Ur, Ui);

    const int smem_bytes = 2 * 4 * 128 * PITB;        // 81920
    cudaFuncSetAttribute(gemm_mma,
                         cudaFuncAttributeMaxDynamicSharedMemorySize, smem_bytes);
    gemm_mma<<<528, 256, smem_bytes>>>();

    trace_kernel<<<1, 256>>>();

    // 5 full sweeps (A->B->A->B->A->B): lc = 10, 8, 6, 4, 2. Result in B.
    int dir = 0;
    for (int n = 1; n <= 5; n++) {
        qmt_sweep<<<4096, 256>>>(dir, Mr, Mi, 12 - 2 * n);
        dir ^= 1;
    }

    // Fused sweep-6 + gather: contract each queried 16-block on the fly.
    int nq = in_sizes[3];
    fused_gather<<<(nq + 255) / 256, 256>>>(idx, Mr, Mi, out, nq);
}